// round 8
// baseline (speedup 1.0000x reference)
#include <cuda_runtime.h>
#include <cuda_bf16.h>
#include <math.h>
#include <stdint.h>

#define BB   128
#define TT   24
#define EE   512
#define HH   512
#define VV   10000
#define G4   2048
#define BTR  3072
#define OUTROW 250000
#define NPAD 10112          // 79 * 128  (padded vocab rows)

// ---------------- device scratch (no allocations allowed) ----------------
__device__ __nv_bfloat16 g_Xhi [BTR * EE], g_Xlo [BTR * EE];     // embedded captions
__device__ __nv_bfloat16 g_Wihhi[G4 * EE], g_Wihlo[G4 * EE];     // permuted W_ih
__device__ __nv_bfloat16 g_Whhhi[G4 * HH], g_Whhlo[G4 * HH];     // permuted W_hh
__device__ __nv_bfloat16 g_Wouthi[NPAD * HH], g_Woutlo[NPAD * HH];
__device__ __nv_bfloat16 g_Hhi [BTR * HH], g_Hlo [BTR * HH];     // all hidden states
__device__ __nv_bfloat16 g_hAhi[BB * HH], g_hAlo[BB * HH];
__device__ __nv_bfloat16 g_hBhi[BB * HH], g_hBlo[BB * HH];
__device__ float g_c   [BB * HH];
__device__ float g_bias[G4];                                     // permuted b_ih+b_hh
__device__ float g_Xg  [BTR * G4];                               // input gates (permuted cols)

// ---------------- small helpers ----------------
__device__ __forceinline__ float sigf(float x) { return 1.0f / (1.0f + expf(-x)); }

__device__ __forceinline__ void split2(float x, __nv_bfloat16& h, __nv_bfloat16& l) {
    h = __float2bfloat16(x);
    l = __float2bfloat16(x - __bfloat162float(h));
}

__device__ __forceinline__ uint32_t smem_to_u32(const void* p) {
    uint32_t a;
    asm("{ .reg .u64 t; cvta.to.shared.u64 t, %1; cvt.u32.u64 %0, t; }" : "=r"(a) : "l"(p));
    return a;
}

// ---------------- warp-level tensor ops (sm_80+ PTX; legal on plain sm_103) ----
__device__ __forceinline__ void ldsm_x4(uint32_t* r, uint32_t addr) {
    asm volatile("ldmatrix.sync.aligned.m8n8.x4.shared.b16 {%0,%1,%2,%3}, [%4];"
                 : "=r"(r[0]), "=r"(r[1]), "=r"(r[2]), "=r"(r[3]) : "r"(addr));
}

__device__ __forceinline__ void mma_bf16(float* c, const uint32_t* a, const uint32_t* b) {
    asm volatile(
        "mma.sync.aligned.m16n8k16.row.col.f32.bf16.bf16.f32 "
        "{%0,%1,%2,%3}, {%4,%5,%6,%7}, {%8,%9}, {%0,%1,%2,%3};"
        : "+f"(c[0]), "+f"(c[1]), "+f"(c[2]), "+f"(c[3])
        : "r"(a[0]), "r"(a[1]), "r"(a[2]), "r"(a[3]), "r"(b[0]), "r"(b[1]));
}

// ---------------- smem layout ----------------
// Tile = 128 rows x 64 bf16 k, rows padded to 72 elems (144B) -> 18432 B/plane.
// Row stride 144B = 36 words; 36 mod 32 = 4 => 8 consecutive rows hit all 32
// banks with their 4-word ldmatrix segments: conflict-free.
#define TILE_B  (128 * 144)
#define SM_AH   0
#define SM_AL   (1 * TILE_B)
#define SM_BH   (2 * TILE_B)
#define SM_BL   (3 * TILE_B)
#define SMEM_DYN (4 * TILE_B)     // 73728 bytes

// Load one 128x64 bf16 tile (gmem ld = 512) into padded smem rows.
__device__ __forceinline__ void load_tile(char* dst, const __nv_bfloat16* src,
                                          int row0, int k0, int tid) {
#pragma unroll
    for (int i = 0; i < 4; i++) {
        int e  = tid + i * 256;           // 0..1023 groups of 8 bf16
        int r  = e >> 3;                  // 0..127
        int k8 = (e & 7) << 3;            // 0..56
        uint4 v = *(const uint4*)(src + (size_t)(row0 + r) * 512 + k0 + k8);
        *(uint4*)(dst + r * 144 + k8 * 2) = v;
    }
}

// ---------------- shared mainloop ----------------
// acc[mi][ni][4] += A(hi+lo)[128xK] @ B(hi+lo)[128xK]^T  (3-product bf16 emulation)
// Warp grid: 8 warps = 2(m) x 4(n); warp tile 64m x 32n; K = 512, K-tile 64.
__device__ __forceinline__ void gemm_mainloop(char* sm,
        const __nv_bfloat16* Ahi, const __nv_bfloat16* Alo, int arow0,
        const __nv_bfloat16* Bhi, const __nv_bfloat16* Blo, int brow0,
        float acc[4][4][4]) {
    const int tid  = threadIdx.x;
    const int lane = tid & 31;
    const int w    = tid >> 5;
    const int wm   = w & 1;
    const int wn   = w >> 1;
    const uint32_t sb = smem_to_u32(sm);

    const int lrow = lane & 15;
    const int lcol = (lane >> 4) * 16;    // byte offset within 32B k16 chunk

    for (int kt = 0; kt < 8; kt++) {
        int k0 = kt * 64;
        load_tile(sm + SM_AH, Ahi, arow0, k0, tid);
        load_tile(sm + SM_AL, Alo, arow0, k0, tid);
        load_tile(sm + SM_BH, Bhi, brow0, k0, tid);
        load_tile(sm + SM_BL, Blo, brow0, k0, tid);
        __syncthreads();

#pragma unroll
        for (int kc = 0; kc < 4; kc++) {
            uint32_t ah[4][4], al[4][4], bh[4][2], bl[4][2];
#pragma unroll
            for (int mi = 0; mi < 4; mi++) {
                uint32_t a = sb + SM_AH + (wm * 64 + mi * 16 + lrow) * 144 + kc * 32 + lcol;
                ldsm_x4(ah[mi], a);
                ldsm_x4(al[mi], a + TILE_B);
            }
#pragma unroll
            for (int n2 = 0; n2 < 2; n2++) {
                uint32_t r0[4], r1[4];
                uint32_t b = sb + SM_BH + (wn * 32 + n2 * 16 + lrow) * 144 + kc * 32 + lcol;
                ldsm_x4(r0, b);
                ldsm_x4(r1, b + TILE_B);
                bh[n2 * 2 + 0][0] = r0[0]; bh[n2 * 2 + 0][1] = r0[2];
                bh[n2 * 2 + 1][0] = r0[1]; bh[n2 * 2 + 1][1] = r0[3];
                bl[n2 * 2 + 0][0] = r1[0]; bl[n2 * 2 + 0][1] = r1[2];
                bl[n2 * 2 + 1][0] = r1[1]; bl[n2 * 2 + 1][1] = r1[3];
            }
#pragma unroll
            for (int mi = 0; mi < 4; mi++)
#pragma unroll
                for (int ni = 0; ni < 4; ni++) {
                    mma_bf16(acc[mi][ni], ah[mi], bh[ni]);
                    mma_bf16(acc[mi][ni], ah[mi], bl[ni]);
                    mma_bf16(acc[mi][ni], al[mi], bh[ni]);
                }
        }
        __syncthreads();
    }
}

// ---------------- generic GEMM kernel (mode 0 plain, 1 logits scatter) ----------------
__global__ __launch_bounds__(256, 1)
void mma_gemm(const __nv_bfloat16* __restrict__ Ahi, const __nv_bfloat16* __restrict__ Alo,
              const __nv_bfloat16* __restrict__ Bhi, const __nv_bfloat16* __restrict__ Blo,
              const float* __restrict__ bias, float* __restrict__ Cout,
              int ldc, int nmax, int mode) {
    extern __shared__ char sm[];
    float acc[4][4][4];
#pragma unroll
    for (int a = 0; a < 4; a++)
#pragma unroll
        for (int b = 0; b < 4; b++)
#pragma unroll
            for (int c = 0; c < 4; c++) acc[a][b][c] = 0.0f;

    gemm_mainloop(sm, Ahi, Alo, blockIdx.y * 128, Bhi, Blo, blockIdx.x * 128, acc);

    const int lane = threadIdx.x & 31;
    const int w    = threadIdx.x >> 5;
    const int wm   = w & 1, wn = w >> 1;

#pragma unroll
    for (int mi = 0; mi < 4; mi++)
#pragma unroll
        for (int ni = 0; ni < 4; ni++) {
            int m = blockIdx.y * 128 + wm * 64 + mi * 16 + (lane >> 2);
            int n = blockIdx.x * 128 + wn * 32 + ni * 8 + (lane & 3) * 2;
            float v0 = acc[mi][ni][0];
            float v1 = acc[mi][ni][1];
            float v2 = acc[mi][ni][2];
            float v3 = acc[mi][ni][3];
            if (mode == 0) {
                Cout[(size_t)m * ldc + n]           = v0 + bias[n];
                Cout[(size_t)m * ldc + n + 1]       = v1 + bias[n + 1];
                Cout[(size_t)(m + 8) * ldc + n]     = v2 + bias[n];
                Cout[(size_t)(m + 8) * ldc + n + 1] = v3 + bias[n + 1];
            } else {
                int t0 = m >> 7, b0 = m & 127;
                int t1 = (m + 8) >> 7, b1 = (m + 8) & 127;
                float* d0 = Cout + (size_t)b0 * OUTROW + (size_t)(t0 + 1) * VV;
                float* d1 = Cout + (size_t)b1 * OUTROW + (size_t)(t1 + 1) * VV;
                if (n < nmax)     { d0[n]     = v0 + bias[n];     d1[n]     = v2 + bias[n]; }
                if (n + 1 < nmax) { d0[n + 1] = v1 + bias[n + 1]; d1[n + 1] = v3 + bias[n + 1]; }
            }
        }
}

// ---------------- LSTM step: gates = h @ Whh'^T + Xg -> cell -> new h ----------------
// Permuted gate cols: np = j*4+g. Within an 8-col n-frag, lanes pair up:
// even lane (t even) holds (i,f), odd holds (g,o) of the same j -> one shfl_xor(1).
__global__ __launch_bounds__(256, 1)
void mma_step(int t) {
    extern __shared__ char sm[];
    const int ping = t & 1;
    const __nv_bfloat16* hih = ping ? g_hBhi : g_hAhi;
    const __nv_bfloat16* hil = ping ? g_hBlo : g_hAlo;
    __nv_bfloat16* hoh = ping ? g_hAhi : g_hBhi;
    __nv_bfloat16* hol = ping ? g_hAlo : g_hBlo;

    float acc[4][4][4];
#pragma unroll
    for (int a = 0; a < 4; a++)
#pragma unroll
        for (int b = 0; b < 4; b++)
#pragma unroll
            for (int c = 0; c < 4; c++) acc[a][b][c] = 0.0f;

    gemm_mainloop(sm, hih, hil, 0, g_Whhhi, g_Whhlo, blockIdx.x * 128, acc);

    const int lane = threadIdx.x & 31;
    const int w    = threadIdx.x >> 5;
    const int wm   = w & 1, wn = w >> 1;
    const int tpar = lane & 1;

#pragma unroll
    for (int mi = 0; mi < 4; mi++)
#pragma unroll
        for (int ni = 0; ni < 4; ni++) {
            int m = wm * 64 + mi * 16 + (lane >> 2);       // batch row (0..119)
            int n = blockIdx.x * 128 + wn * 32 + ni * 8 + (lane & 3) * 2;  // permuted gate col
            int r = t * 128 + m;
            const float* xg = g_Xg + (size_t)r * G4;

            float c0 = acc[mi][ni][0] + xg[n];
            float c1 = acc[mi][ni][1] + xg[n + 1];
            float c2 = acc[mi][ni][2] + xg[8 * G4 + n];
            float c3 = acc[mi][ni][3] + xg[8 * G4 + n + 1];

            float e0 = __shfl_xor_sync(0xFFFFFFFFu, c0, 1);
            float e1 = __shfl_xor_sync(0xFFFFFFFFu, c1, 1);
            float e2 = __shfl_xor_sync(0xFFFFFFFFu, c2, 1);
            float e3 = __shfl_xor_sync(0xFFFFFFFFu, c3, 1);

            int   row, j = n >> 2;
            float iv, fv, gv, ov;
            if (!tpar) { row = m;     iv = c0; fv = c1; gv = e0; ov = e1; }
            else       { row = m + 8; iv = e2; fv = e3; gv = c2; ov = c3; }

            float cO = g_c[row * HH + j];
            float cN = sigf(fv) * cO + sigf(iv) * tanhf(gv);
            float hN = sigf(ov) * tanhf(cN);
            g_c[row * HH + j] = cN;

            __nv_bfloat16 hh, hl;
            split2(hN, hh, hl);
            hoh[row * HH + j] = hh;
            hol[row * HH + j] = hl;
            int rr = t * 128 + row;
            g_Hhi[(size_t)rr * HH + j] = hh;
            g_Hlo[(size_t)rr * HH + j] = hl;
        }
}

// ---------------- prep kernels ----------------
__global__ void k_init(const float* __restrict__ img,
                       const float* __restrict__ bih,
                       const float* __restrict__ bhh) {
    int i = blockIdx.x * blockDim.x + threadIdx.x;
    if (i < BB * HH) {
        __nv_bfloat16 h, l;
        split2(img[i], h, l);
        g_hAhi[i] = h; g_hAlo[i] = l;
        g_c[i] = 0.0f;
    }
    if (i < G4) {   // permuted bias: rp = j*4+g  <-  g*512+j
        int j = i >> 2, g = i & 3;
        g_bias[i] = bih[g * HH + j] + bhh[g * HH + j];
    }
}

__global__ void k_embed(const int* __restrict__ caps, const float* __restrict__ Wemb) {
    int idx = blockIdx.x * blockDim.x + threadIdx.x;    // over BTR*128 float4 groups
    if (idx >= BTR * 128) return;
    int e4 = idx & 127, r = idx >> 7;
    int t = r >> 7, b = r & 127;
    int tok = caps[b * TT + t];
    float4 v = make_float4(0.f, 0.f, 0.f, 0.f);
    if (tok != 0) v = *(const float4*)(Wemb + (size_t)tok * EE + e4 * 4);
    int base = r * EE + e4 * 4;
    __nv_bfloat16 h, l;
    split2(v.x, h, l); g_Xhi[base + 0] = h; g_Xlo[base + 0] = l;
    split2(v.y, h, l); g_Xhi[base + 1] = h; g_Xlo[base + 1] = l;
    split2(v.z, h, l); g_Xhi[base + 2] = h; g_Xlo[base + 2] = l;
    split2(v.w, h, l); g_Xhi[base + 3] = h; g_Xlo[base + 3] = l;
}

// permuted split for W_ih / W_hh: dst row rp = j*4+g <- src row g*512+j
__global__ void k_split_perm(const float* __restrict__ W,
                             __nv_bfloat16* __restrict__ hi,
                             __nv_bfloat16* __restrict__ lo) {
    int idx = blockIdx.x * blockDim.x + threadIdx.x;    // over G4*128 float4 groups
    if (idx >= G4 * 128) return;
    int k4 = idx & 127, rp = idx >> 7;
    int j = rp >> 2, g = rp & 3;
    float4 v = *(const float4*)(W + (size_t)(g * HH + j) * 512 + k4 * 4);
    int base = rp * 512 + k4 * 4;
    __nv_bfloat16 h, l;
    split2(v.x, h, l); hi[base + 0] = h; lo[base + 0] = l;
    split2(v.y, h, l); hi[base + 1] = h; lo[base + 1] = l;
    split2(v.z, h, l); hi[base + 2] = h; lo[base + 2] = l;
    split2(v.w, h, l); hi[base + 3] = h; lo[base + 3] = l;
}

__global__ void k_split_out(const float* __restrict__ W) {
    int idx = blockIdx.x * blockDim.x + threadIdx.x;    // over NPAD*128 float4 groups
    if (idx >= NPAD * 128) return;
    int k4 = idx & 127, r = idx >> 7;
    float4 v = make_float4(0.f, 0.f, 0.f, 0.f);
    if (r < VV) v = *(const float4*)(W + (size_t)r * HH + k4 * 4);
    int base = r * 512 + k4 * 4;
    __nv_bfloat16 h, l;
    split2(v.x, h, l); g_Wouthi[base + 0] = h; g_Woutlo[base + 0] = l;
    split2(v.y, h, l); g_Wouthi[base + 1] = h; g_Woutlo[base + 1] = l;
    split2(v.z, h, l); g_Wouthi[base + 2] = h; g_Woutlo[base + 2] = l;
    split2(v.w, h, l); g_Wouthi[base + 3] = h; g_Woutlo[base + 3] = l;
}

__global__ void k_start(float* __restrict__ out, const int* __restrict__ clen, int extra) {
    int i = blockIdx.x * blockDim.x + threadIdx.x;
    const int n = BB * VV;
    if (i < n) {
        int b = i / VV;
        int v = i - b * VV;
        out[(size_t)b * OUTROW + v] = (v == 1) ? 1.0f : 0.0f;
    }
    if (i < extra) {
        float val = (i < BB) ? (float)(clen[i] - 1) : 0.0f;
        out[(size_t)BB * OUTROW + i] = val;
    }
}

// ---------------- launch ----------------
extern "C" void kernel_launch(void* const* d_in, const int* in_sizes, int n_in,
                              void* d_out, int out_size) {
    const float* images = (const float*)d_in[0];
    const int*   caps   = (const int*)  d_in[1];
    const int*   clen   = (const int*)  d_in[2];
    const float* Wemb   = (const float*)d_in[3];
    const float* Wih    = (const float*)d_in[4];
    const float* Whh    = (const float*)d_in[5];
    const float* bih    = (const float*)d_in[6];
    const float* bhh    = (const float*)d_in[7];
    const float* Wout   = (const float*)d_in[8];
    const float* bout   = (const float*)d_in[9];
    float* out = (float*)d_out;

    cudaFuncSetAttribute(mma_gemm, cudaFuncAttributeMaxDynamicSharedMemorySize, SMEM_DYN);
    cudaFuncSetAttribute(mma_step, cudaFuncAttributeMaxDynamicSharedMemorySize, SMEM_DYN);

    const __nv_bfloat16 *pXhi, *pXlo, *pWihhi, *pWihlo, *pWouthi, *pWoutlo, *pHhi, *pHlo;
    float *pbias, *pXg;
    cudaGetSymbolAddress((void**)&pXhi,    g_Xhi);
    cudaGetSymbolAddress((void**)&pXlo,    g_Xlo);
    cudaGetSymbolAddress((void**)&pWihhi,  g_Wihhi);
    cudaGetSymbolAddress((void**)&pWihlo,  g_Wihlo);
    cudaGetSymbolAddress((void**)&pWouthi, g_Wouthi);
    cudaGetSymbolAddress((void**)&pWoutlo, g_Woutlo);
    cudaGetSymbolAddress((void**)&pHhi,    g_Hhi);
    cudaGetSymbolAddress((void**)&pHlo,    g_Hlo);
    cudaGetSymbolAddress((void**)&pbias,   g_bias);
    cudaGetSymbolAddress((void**)&pXg,     g_Xg);

    __nv_bfloat16 *pWhhhi, *pWhhlo;
    cudaGetSymbolAddress((void**)&pWhhhi, g_Whhhi);
    cudaGetSymbolAddress((void**)&pWhhlo, g_Whhlo);

    // 1. init: h0 planes, c0, permuted bias
    k_init<<<(BB * HH + 255) / 256, 256>>>(images, bih, bhh);

    // 2. embedding -> bf16 hi/lo planes
    k_embed<<<(BTR * 128 + 255) / 256, 256>>>(caps, Wemb);

    // 3. weight splits
    k_split_perm<<<(G4 * 128 + 255) / 256, 256>>>(Wih, (__nv_bfloat16*)pWihhi, (__nv_bfloat16*)pWihlo);
    k_split_perm<<<(G4 * 128 + 255) / 256, 256>>>(Whh, pWhhhi, pWhhlo);
    k_split_out <<<(NPAD * 128 + 255) / 256, 256>>>(Wout);

    // 4. Xg = X @ Wih'^T + bias'   [3072 x 2048]
    {
        dim3 grid(G4 / 128, BTR / 128);
        mma_gemm<<<grid, 256, SMEM_DYN>>>(pXhi, pXlo, pWihhi, pWihlo,
                                          pbias, pXg, G4, G4, 0);
    }

    // 5. recurrence: 24 HMMA steps with fused cell epilogue
    for (int t = 0; t < TT; t++)
        mma_step<<<dim3(G4 / 128, 1), 256, SMEM_DYN>>>(t);

    // 6. logits = H_all @ Wout^T + b_out -> scatter into d_out
    {
        dim3 grid(NPAD / 128, BTR / 128);
        mma_gemm<<<grid, 256, SMEM_DYN>>>(pHhi, pHlo, pWouthi, pWoutlo,
                                          bout, out, VV, VV, 1);
    }

    // 7. t=0 one-hot rows + optional length tail
    {
        int extra = out_size - BB * OUTROW;
        if (extra < 0) extra = 0;
        k_start<<<(BB * VV + 255) / 256, 256>>>(out, clen, extra);
    }
}